// round 9
// baseline (speedup 1.0000x reference)
#include <cuda_runtime.h>
#include <cuda_fp16.h>
#include <cstdint>
#include <math.h>

// Problem constants
#define B_SZ 65536
#define IN2  256
#define H2   512
#define G3   1536
#define NQ   64

#define ACT_NONE 0
#define ACT_RELU 1

// ---------------------------------------------------------------------------
// Scratch (__device__ globals; allocation-free rule)
// ---------------------------------------------------------------------------
__device__ __half g_x_h  [(size_t)B_SZ * H2];    // fc1 output, fp16
__device__ __half g_hp_h [(size_t)B_SZ * H2];    // h' fp16 (for head GEMM)
__device__ __half g_W1h  [H2 * IN2];             // W1 fp16
// Packed GRU weights: [16 jblocks][96 rows][1024 cols] fp16.
//   rows  0..31 : r band  [W_ih_r | W_hh_r]
//   rows 32..63 : z band  [W_ih_z | W_hh_z]
//   rows 64..95 : n band  [W_ih_n | W_hh_n]  (K-halves -> separate accums)
__device__ __half g_wpack[16 * 96 * 1024];
__device__ float  g_br [H2];   // b_ih_r + b_hh_r
__device__ float  g_bz [H2];   // b_ih_z + b_hh_z
__device__ float  g_bin[H2];   // b_ih_n
__device__ float  g_bhn[H2];   // b_hh_n
__device__ __half g_wcat_h[NQ * H2];
__device__ float  g_bcat [NQ];

// ---------------------------------------------------------------------------
// fp32 -> fp16 conversion (for W1 only now)
// ---------------------------------------------------------------------------
__global__ void f2h_kernel(const float* __restrict__ src,
                           __half* __restrict__ dst, int n4)
{
    int i = blockIdx.x * blockDim.x + threadIdx.x;
    if (i < n4) {
        float4 v = ((const float4*)src)[i];
        ((__half2*)dst)[2 * i]     = __floats2half2_rn(v.x, v.y);
        ((__half2*)dst)[2 * i + 1] = __floats2half2_rn(v.z, v.w);
    }
}

// Pack GRU weights into banded layout + combined biases.
__global__ void pack_gru_kernel(const float* __restrict__ W_ih,
                                const float* __restrict__ W_hh,
                                const float* __restrict__ b_ih,
                                const float* __restrict__ b_hh)
{
    const int i = blockIdx.x * blockDim.x + threadIdx.x;
    const int TOT = 16 * 96 * 1024;
    if (i < TOT) {
        const int jb   = i / (96 * 1024);
        const int rem  = i % (96 * 1024);
        const int brow = rem / 1024;
        const int k    = rem % 1024;
        const int band = brow / 32;              // 0=r,1=z,2=n
        const int j    = jb * 32 + (brow % 32);  // hidden column
        const float* src = (k < 512) ? W_ih : W_hh;
        g_wpack[i] = __float2half_rn(src[(size_t)(band * 512 + j) * 512 + (k & 511)]);
    }
    if (i < H2) {
        g_br [i] = b_ih[i]        + b_hh[i];
        g_bz [i] = b_ih[512 + i]  + b_hh[512 + i];
        g_bin[i] = b_ih[1024 + i];
        g_bhn[i] = b_hh[1024 + i];
    }
}

// Pack concat(W21,W22) fp16 + concat(b21,b22) fp32.
__global__ void pack_heads_kernel(const float* __restrict__ W21,
                                  const float* __restrict__ b21,
                                  const float* __restrict__ W22,
                                  const float* __restrict__ b22)
{
    const int i = blockIdx.x * blockDim.x + threadIdx.x;
    if (i < NQ * H2) {
        const int r = i / H2;
        const int c = i % H2;
        float v = (r < 32) ? W21[r * H2 + c] : W22[(r - 32) * H2 + c];
        g_wcat_h[i] = __float2half_rn(v);
    }
    if (i < NQ)
        g_bcat[i] = (i < 32) ? b21[i] : b22[i - 32];
}

#define MMA_F16(acc, av, bv)                                                   \
    asm volatile(                                                              \
        "mma.sync.aligned.m16n8k16.row.col.f32.f16.f16.f32 "                   \
        "{%0,%1,%2,%3}, {%4,%5,%6,%7}, {%8,%9}, {%0,%1,%2,%3};"                \
        : "+f"((acc)[0]), "+f"((acc)[1]), "+f"((acc)[2]), "+f"((acc)[3])       \
        : "r"((av)[0]), "r"((av)[1]), "r"((av)[2]), "r"((av)[3]),              \
          "r"((bv)[0]), "r"((bv)[1]))

// ---------------------------------------------------------------------------
// Tensor-core GEMM: C[M,N] = act(A[M,K] @ W[N,K]^T + bias[N])
// A optionally fp32 in gmem (converted during tile load).
// ---------------------------------------------------------------------------
template <int WM, int WN, int ACT, bool OUT_HALF, bool A_F32>
__global__ __launch_bounds__(256, 2) void hgemm_kernel(
    const void* __restrict__ Ain, const __half* __restrict__ W,
    const float* __restrict__ bias, void* __restrict__ Cout,
    int M, int N, int K)
{
    constexpr int BM = WM * 64;
    constexpr int BN = WN * 32;
    constexpr int BK = 32;
    constexpr int LDK = 40;

    __shared__ __align__(16) __half As[BM][LDK];
    __shared__ __align__(16) __half Bs[BN][LDK];

    const int tid  = threadIdx.x;
    const int warp = tid >> 5, lane = tid & 31;
    const int g = lane >> 2, t = lane & 3;
    const int wm = warp / WN, wn = warp % WN;
    const int bm = blockIdx.y * BM, bn = blockIdx.x * BN;
    const int row0 = wm * 64, col0 = wn * 32;

    float acc[4][4][4];
#pragma unroll
    for (int i = 0; i < 4; i++)
#pragma unroll
        for (int j = 0; j < 4; j++)
#pragma unroll
            for (int q = 0; q < 4; q++) acc[i][j][q] = 0.0f;

    for (int k0 = 0; k0 < K; k0 += BK) {
#pragma unroll
        for (int it = 0; it < BM / 64; ++it) {
            int idx = tid + it * 256;
            int r = idx >> 2, c = (idx & 3) * 8;
            if (A_F32) {
                const float* Af = (const float*)Ain + (size_t)(bm + r) * K + k0 + c;
                float4 v0 = *(const float4*)Af;
                float4 v1 = *(const float4*)(Af + 4);
                __half2* d = (__half2*)&As[r][c];
                d[0] = __floats2half2_rn(v0.x, v0.y);
                d[1] = __floats2half2_rn(v0.z, v0.w);
                d[2] = __floats2half2_rn(v1.x, v1.y);
                d[3] = __floats2half2_rn(v1.z, v1.w);
            } else {
                *(uint4*)&As[r][c] =
                    *(const uint4*)((const __half*)Ain + (size_t)(bm + r) * K + k0 + c);
            }
        }
#pragma unroll
        for (int it = 0; it < BN / 64; ++it) {
            int idx = tid + it * 256;
            int r = idx >> 2, c = (idx & 3) * 8;
            *(uint4*)&Bs[r][c] =
                *(const uint4*)(W + (size_t)(bn + r) * K + k0 + c);
        }
        __syncthreads();

#pragma unroll
        for (int kf = 0; kf < 2; ++kf) {
            const int kb = kf * 16;
            uint32_t a[4][4], b[4][2];
#pragma unroll
            for (int i = 0; i < 4; i++) {
                int r = row0 + i * 16 + g;
                a[i][0] = *(const uint32_t*)&As[r][kb + 2 * t];
                a[i][1] = *(const uint32_t*)&As[r + 8][kb + 2 * t];
                a[i][2] = *(const uint32_t*)&As[r][kb + 2 * t + 8];
                a[i][3] = *(const uint32_t*)&As[r + 8][kb + 2 * t + 8];
            }
#pragma unroll
            for (int j = 0; j < 4; j++) {
                int c = col0 + j * 8 + g;
                b[j][0] = *(const uint32_t*)&Bs[c][kb + 2 * t];
                b[j][1] = *(const uint32_t*)&Bs[c][kb + 2 * t + 8];
            }
#pragma unroll
            for (int i = 0; i < 4; i++)
#pragma unroll
                for (int j = 0; j < 4; j++)
                    MMA_F16(acc[i][j], a[i], b[j]);
        }
        __syncthreads();
    }

#pragma unroll
    for (int i = 0; i < 4; i++) {
#pragma unroll
        for (int j = 0; j < 4; j++) {
            const int c = bn + col0 + j * 8 + 2 * t;
            const float bx = bias[c], by = bias[c + 1];
            float v0 = acc[i][j][0] + bx, v1 = acc[i][j][1] + by;
            float v2 = acc[i][j][2] + bx, v3 = acc[i][j][3] + by;
            if (ACT == ACT_RELU) {
                v0 = fmaxf(v0, 0.f); v1 = fmaxf(v1, 0.f);
                v2 = fmaxf(v2, 0.f); v3 = fmaxf(v3, 0.f);
            }
            const int r0 = bm + row0 + i * 16 + g;
            if (OUT_HALF) {
                __half2* C = (__half2*)Cout;
                C[((size_t)r0 * N + c) >> 1]       = __floats2half2_rn(v0, v1);
                C[((size_t)(r0 + 8) * N + c) >> 1] = __floats2half2_rn(v2, v3);
            } else {
                float* C = (float*)Cout;
                float2 o0 = {v0, v1}, o1 = {v2, v3};
                *(float2*)&C[(size_t)r0 * N + c]       = o0;
                *(float2*)&C[(size_t)(r0 + 8) * N + c] = o1;
            }
        }
    }
}

__device__ __forceinline__ float sigmoidf_(float x) {
    return 1.0f / (1.0f + __expf(-x));
}

// ---------------------------------------------------------------------------
// Fused GRU kernel: computes gi, gh and the gate nonlinearity in one pass.
// Block = 128 batch rows x 32 hidden cols (jblock). 8 warps; each warp owns
// 32 rows x 16 cols x all 4 accumulator bands (warp-local epilogue).
// A = [x | hidden] over K=1024 (x fp16 from fc1; hidden fp32 converted in-tile).
// Bands: r,z accumulate over full K; n band accumulates into i_n for K<512
// and h_n for K>=512 (same smem weight rows, different accumulators).
// ---------------------------------------------------------------------------
__global__ __launch_bounds__(256, 2) void gru_fused_kernel(
    const __half* __restrict__ xh, const float* __restrict__ hidden,
    float* __restrict__ h_out, __half* __restrict__ h_out_h)
{
    __shared__ __align__(16) __half As[128][40];
    __shared__ __align__(16) __half Ws[96][40];

    const int tid  = threadIdx.x;
    const int warp = tid >> 5, lane = tid & 31;
    const int g = lane >> 2, t = lane & 3;
    const int mi = warp >> 1, ji = warp & 1;   // 4 m-tiles x 2 j-tiles
    const int bm = blockIdx.y * 128;
    const int jb = blockIdx.x;                 // 0..15
    const __half* wpack = g_wpack + (size_t)jb * 96 * 1024;

    float ar[2][2][4], az[2][2][4], ain[2][2][4], ahn[2][2][4];
#pragma unroll
    for (int i = 0; i < 2; i++)
#pragma unroll
        for (int j = 0; j < 2; j++)
#pragma unroll
            for (int q = 0; q < 4; q++) {
                ar[i][j][q] = 0.f; az[i][j][q] = 0.f;
                ain[i][j][q] = 0.f; ahn[i][j][q] = 0.f;
            }

    for (int k0 = 0; k0 < 1024; k0 += 32) {
        // A tile: 128 x 32 halves
        if (k0 < 512) {
#pragma unroll
            for (int it = 0; it < 2; ++it) {
                int idx = tid + it * 256;
                int r = idx >> 2, c = (idx & 3) * 8;
                *(uint4*)&As[r][c] =
                    *(const uint4*)(xh + (size_t)(bm + r) * H2 + k0 + c);
            }
        } else {
#pragma unroll
            for (int it = 0; it < 2; ++it) {
                int idx = tid + it * 256;
                int r = idx >> 2, c = (idx & 3) * 8;
                const float* src = hidden + (size_t)(bm + r) * H2 + (k0 - 512) + c;
                float4 v0 = *(const float4*)src;
                float4 v1 = *(const float4*)(src + 4);
                __half2* d = (__half2*)&As[r][c];
                d[0] = __floats2half2_rn(v0.x, v0.y);
                d[1] = __floats2half2_rn(v0.z, v0.w);
                d[2] = __floats2half2_rn(v1.x, v1.y);
                d[3] = __floats2half2_rn(v1.z, v1.w);
            }
        }
        // W tile: 96 x 32 halves (384 uint4 chunks over 256 threads)
#pragma unroll
        for (int it = 0; it < 2; ++it) {
            int idx = tid + it * 256;
            if (idx < 384) {
                int r = idx >> 2, c = (idx & 3) * 8;
                *(uint4*)&Ws[r][c] =
                    *(const uint4*)(wpack + (size_t)r * 1024 + k0 + c);
            }
        }
        __syncthreads();

        const bool first_half = (k0 < 512);
#pragma unroll
        for (int kf = 0; kf < 2; ++kf) {
            const int kb = kf * 16;
            uint32_t a[2][4];
#pragma unroll
            for (int i = 0; i < 2; i++) {
                int r = mi * 32 + i * 16 + g;
                a[i][0] = *(const uint32_t*)&As[r][kb + 2 * t];
                a[i][1] = *(const uint32_t*)&As[r + 8][kb + 2 * t];
                a[i][2] = *(const uint32_t*)&As[r][kb + 2 * t + 8];
                a[i][3] = *(const uint32_t*)&As[r + 8][kb + 2 * t + 8];
            }
            uint32_t br_[2][2], bz_[2][2], bn_[2][2];
#pragma unroll
            for (int j = 0; j < 2; j++) {
                int c = ji * 16 + j * 8 + g;
                br_[j][0] = *(const uint32_t*)&Ws[c][kb + 2 * t];
                br_[j][1] = *(const uint32_t*)&Ws[c][kb + 2 * t + 8];
                bz_[j][0] = *(const uint32_t*)&Ws[32 + c][kb + 2 * t];
                bz_[j][1] = *(const uint32_t*)&Ws[32 + c][kb + 2 * t + 8];
                bn_[j][0] = *(const uint32_t*)&Ws[64 + c][kb + 2 * t];
                bn_[j][1] = *(const uint32_t*)&Ws[64 + c][kb + 2 * t + 8];
            }
#pragma unroll
            for (int i = 0; i < 2; i++)
#pragma unroll
                for (int j = 0; j < 2; j++) {
                    MMA_F16(ar[i][j], a[i], br_[j]);
                    MMA_F16(az[i][j], a[i], bz_[j]);
                    if (first_half) MMA_F16(ain[i][j], a[i], bn_[j]);
                    else            MMA_F16(ahn[i][j], a[i], bn_[j]);
                }
        }
        __syncthreads();
    }

    // Warp-local gate epilogue
    const int jbase = jb * 32 + ji * 16;
#pragma unroll
    for (int i = 0; i < 2; i++) {
#pragma unroll
        for (int j = 0; j < 2; j++) {
            const int col = jbase + j * 8 + 2 * t;
            const float2 brv  = *(const float2*)&g_br [col];
            const float2 bzv  = *(const float2*)&g_bz [col];
            const float2 binv = *(const float2*)&g_bin[col];
            const float2 bhnv = *(const float2*)&g_bhn[col];
#pragma unroll
            for (int hrow = 0; hrow < 2; hrow++) {
                const int row = bm + mi * 32 + i * 16 + g + hrow * 8;
                const int q0 = hrow * 2;
                const float2 hv = *(const float2*)&hidden[(size_t)row * H2 + col];
                float r0 = sigmoidf_(ar[i][j][q0]     + brv.x);
                float r1 = sigmoidf_(ar[i][j][q0 + 1] + brv.y);
                float z0 = sigmoidf_(az[i][j][q0]     + bzv.x);
                float z1 = sigmoidf_(az[i][j][q0 + 1] + bzv.y);
                float n0 = tanhf(ain[i][j][q0]     + binv.x + r0 * (ahn[i][j][q0]     + bhnv.x));
                float n1 = tanhf(ain[i][j][q0 + 1] + binv.y + r1 * (ahn[i][j][q0 + 1] + bhnv.y));
                float o0 = (1.0f - z0) * n0 + z0 * hv.x;
                float o1 = (1.0f - z1) * n1 + z1 * hv.y;
                float2 of = {o0, o1};
                *(float2*)&h_out[(size_t)row * H2 + col] = of;
                *((__half2*)&h_out_h[(size_t)row * H2 + col]) = __floats2half2_rn(o0, o1);
            }
        }
    }
}

// ---------------------------------------------------------------------------
// kernel_launch
// ---------------------------------------------------------------------------
extern "C" void kernel_launch(void* const* d_in, const int* in_sizes, int n_in,
                              void* d_out, int out_size)
{
    const float* inputs = (const float*)d_in[0];
    const float* hidden = (const float*)d_in[1];
    const float* W1     = (const float*)d_in[2];
    const float* b1     = (const float*)d_in[3];
    const float* W_ih   = (const float*)d_in[4];
    const float* W_hh   = (const float*)d_in[5];
    const float* b_ih   = (const float*)d_in[6];
    const float* b_hh   = (const float*)d_in[7];
    const float* W21    = (const float*)d_in[8];
    const float* b21    = (const float*)d_in[9];
    const float* W22    = (const float*)d_in[10];
    const float* b22    = (const float*)d_in[11];

    float* out_q = (float*)d_out;                   // [2B, 32] interleaved
    float* out_h = out_q + (size_t)2 * B_SZ * 32;   // [B, H2]

    __half *xh, *hph, *w1h, *wcath;
    float *bcat;
    cudaGetSymbolAddress((void**)&xh,    g_x_h);
    cudaGetSymbolAddress((void**)&hph,   g_hp_h);
    cudaGetSymbolAddress((void**)&w1h,   g_W1h);
    cudaGetSymbolAddress((void**)&wcath, g_wcat_h);
    cudaGetSymbolAddress((void**)&bcat,  g_bcat);

    // Weight packing / conversion (small, one-shot)
    pack_gru_kernel<<<(16 * 96 * 1024 + 255) / 256, 256>>>(W_ih, W_hh, b_ih, b_hh);
    f2h_kernel<<<(H2 * IN2 / 4 + 255) / 256, 256>>>(W1, w1h, H2 * IN2 / 4);
    pack_heads_kernel<<<(NQ * H2 + 255) / 256, 256>>>(W21, b21, W22, b22);

    // fc1: x = relu(inputs @ W1^T + b1); fp32 A converted in-tile, fp16 out
    hgemm_kernel<2, 4, ACT_RELU, true, true><<<dim3(H2 / 128, B_SZ / 128), 256>>>(
        inputs, w1h, b1, xh, B_SZ, H2, IN2);

    // Fused GRU: gi + gh + gates -> h' (fp32 to out, fp16 for heads)
    gru_fused_kernel<<<dim3(16, B_SZ / 128), 256>>>(xh, hidden, out_h, hph);

    // q heads: out_q = h' @ Wcat^T + bcat  [B,64] == interleaved q
    hgemm_kernel<4, 2, ACT_NONE, false, false><<<dim3(NQ / 64, B_SZ / 256), 256>>>(
        hph, wcath, bcat, out_q, B_SZ, NQ, H2);
}

// round 12
// speedup vs baseline: 1.2570x; 1.2570x over previous
#include <cuda_runtime.h>
#include <cuda_fp16.h>
#include <cstdint>
#include <math.h>

// Problem constants
#define B_SZ 65536
#define IN2  256
#define H2   512
#define G3   1536
#define NQ   64

#define ACT_NONE 0
#define ACT_RELU 1

// ---------------------------------------------------------------------------
// Scratch (__device__ globals; allocation-free rule)
// ---------------------------------------------------------------------------
__device__ __half g_in_h [(size_t)B_SZ * IN2];   // inputs fp16
__device__ __half g_hid_h[(size_t)B_SZ * H2];    // hidden fp16
__device__ __half g_x_h  [(size_t)B_SZ * H2];    // fc1 out fp16
__device__ __half g_hp_h [(size_t)B_SZ * H2];    // h' fp16 (for head GEMM)
__device__ float  g_gi   [(size_t)B_SZ * G3];
__device__ float  g_gh   [(size_t)B_SZ * G3];
__device__ __half g_W1h  [H2 * IN2];
__device__ __half g_Wih_h[G3 * H2];
__device__ __half g_Whh_h[G3 * H2];
__device__ __half g_wcat_h[NQ * H2];
__device__ float  g_bcat [NQ];

// ---------------------------------------------------------------------------
// fp32 -> fp16 conversion
// ---------------------------------------------------------------------------
__global__ void f2h_kernel(const float* __restrict__ src,
                           __half* __restrict__ dst, int n4)
{
    int i = blockIdx.x * blockDim.x + threadIdx.x;
    if (i < n4) {
        float4 v = ((const float4*)src)[i];
        ((__half2*)dst)[2 * i]     = __floats2half2_rn(v.x, v.y);
        ((__half2*)dst)[2 * i + 1] = __floats2half2_rn(v.z, v.w);
    }
}

// Pack concat(W21,W22) to fp16 + concat(b21,b22) fp32.
__global__ void pack_heads_kernel(const float* __restrict__ W21,
                                  const float* __restrict__ b21,
                                  const float* __restrict__ W22,
                                  const float* __restrict__ b22)
{
    const int i = blockIdx.x * blockDim.x + threadIdx.x;
    if (i < NQ * H2) {
        const int r = i / H2;
        const int c = i % H2;
        float v = (r < 32) ? W21[r * H2 + c] : W22[(r - 32) * H2 + c];
        g_wcat_h[i] = __float2half_rn(v);
    }
    if (i < NQ)
        g_bcat[i] = (i < 32) ? b21[i] : b22[i - 32];
}

__device__ __forceinline__ void cp_async16(void* smem, const void* gmem) {
    unsigned sa = (unsigned)__cvta_generic_to_shared(smem);
    asm volatile("cp.async.cg.shared.global [%0], [%1], 16;" :: "r"(sa), "l"(gmem));
}

#define MMA_F16(acc, av, bv)                                                   \
    asm volatile(                                                              \
        "mma.sync.aligned.m16n8k16.row.col.f32.f16.f16.f32 "                   \
        "{%0,%1,%2,%3}, {%4,%5,%6,%7}, {%8,%9}, {%0,%1,%2,%3};"                \
        : "+f"((acc)[0]), "+f"((acc)[1]), "+f"((acc)[2]), "+f"((acc)[3])       \
        : "r"((av)[0]), "r"((av)[1]), "r"((av)[2]), "r"((av)[3]),              \
          "r"((bv)[0]), "r"((bv)[1]))

// ---------------------------------------------------------------------------
// Tensor-core GEMM: C[M,N] = act(A[M,K] @ W[N,K]^T + bias[N])
// fp16 in, fp32 accum. 8 warps, warp tile 64x32; BM=WM*64, BN=WN*32, BK=32.
// PIPE: 2-stage cp.async double-buffered mainloop (overlap LDG with MMA).
// ---------------------------------------------------------------------------
template <int WM, int WN, int ACT, bool OUT_HALF, bool PIPE>
__global__ __launch_bounds__(256, 2) void hgemm_kernel(
    const __half* __restrict__ A, const __half* __restrict__ W,
    const float* __restrict__ bias, void* __restrict__ Cout,
    int M, int N, int K)
{
    constexpr int BM = WM * 64;
    constexpr int BN = WN * 32;
    constexpr int BK = 32;
    constexpr int LDK = 40;
    constexpr int STAGES = PIPE ? 2 : 1;

    __shared__ __align__(16) __half As[STAGES][BM][LDK];
    __shared__ __align__(16) __half Bs[STAGES][BN][LDK];

    const int tid  = threadIdx.x;
    const int warp = tid >> 5, lane = tid & 31;
    const int g = lane >> 2, t = lane & 3;
    const int wm = warp / WN, wn = warp % WN;
    const int bm = blockIdx.y * BM, bn = blockIdx.x * BN;
    const int row0 = wm * 64, col0 = wn * 32;

    float acc[4][4][4];
#pragma unroll
    for (int i = 0; i < 4; i++)
#pragma unroll
        for (int j = 0; j < 4; j++)
#pragma unroll
            for (int q = 0; q < 4; q++) acc[i][j][q] = 0.0f;

    // Per-thread load coordinates (8 halves = 16B per chunk)
    const int lr_a = tid >> 2, lc = (tid & 3) * 8;
    const int lr_b = tid >> 2;

    auto compute_stage = [&](int s) {
#pragma unroll
        for (int kf = 0; kf < 2; ++kf) {
            const int kb = kf * 16;
            uint32_t a[4][4], b[4][2];
#pragma unroll
            for (int i = 0; i < 4; i++) {
                int r = row0 + i * 16 + g;
                a[i][0] = *(const uint32_t*)&As[s][r][kb + 2 * t];
                a[i][1] = *(const uint32_t*)&As[s][r + 8][kb + 2 * t];
                a[i][2] = *(const uint32_t*)&As[s][r][kb + 2 * t + 8];
                a[i][3] = *(const uint32_t*)&As[s][r + 8][kb + 2 * t + 8];
            }
#pragma unroll
            for (int j = 0; j < 4; j++) {
                int c = col0 + j * 8 + g;
                b[j][0] = *(const uint32_t*)&Bs[s][c][kb + 2 * t];
                b[j][1] = *(const uint32_t*)&Bs[s][c][kb + 2 * t + 8];
            }
#pragma unroll
            for (int i = 0; i < 4; i++)
#pragma unroll
                for (int j = 0; j < 4; j++)
                    MMA_F16(acc[i][j], a[i], b[j]);
        }
    };

    if (PIPE) {
        auto load_stage = [&](int s, int k0) {
#pragma unroll
            for (int it = 0; it < BM / 64; ++it) {
                int r = lr_a + it * 64;
                cp_async16(&As[s][r][lc],
                           A + (size_t)(bm + r) * K + k0 + lc);
            }
#pragma unroll
            for (int it = 0; it < BN / 64; ++it) {
                int r = lr_b + it * 64;
                cp_async16(&Bs[s][r][lc],
                           W + (size_t)(bn + r) * K + k0 + lc);
            }
        };

        const int NT = K / BK;
        load_stage(0, 0);
        asm volatile("cp.async.commit_group;");

        for (int kt = 0; kt < NT; ++kt) {
            const int cur = kt & 1;
            if (kt + 1 < NT) {
                load_stage(cur ^ 1, (kt + 1) * BK);
                asm volatile("cp.async.commit_group;");
                asm volatile("cp.async.wait_group 1;");
            } else {
                asm volatile("cp.async.wait_group 0;");
            }
            __syncthreads();
            compute_stage(cur);
            __syncthreads();
        }
    } else {
        for (int k0 = 0; k0 < K; k0 += BK) {
#pragma unroll
            for (int it = 0; it < BM / 64; ++it) {
                int r = lr_a + it * 64;
                *(uint4*)&As[0][r][lc] =
                    *(const uint4*)(A + (size_t)(bm + r) * K + k0 + lc);
            }
#pragma unroll
            for (int it = 0; it < BN / 64; ++it) {
                int r = lr_b + it * 64;
                *(uint4*)&Bs[0][r][lc] =
                    *(const uint4*)(W + (size_t)(bn + r) * K + k0 + lc);
            }
            __syncthreads();
            compute_stage(0);
            __syncthreads();
        }
    }

    // Epilogue: acc[i][j]: {row g, cols 2t,2t+1} and {row g+8, cols 2t,2t+1}
#pragma unroll
    for (int i = 0; i < 4; i++) {
#pragma unroll
        for (int j = 0; j < 4; j++) {
            const int c = bn + col0 + j * 8 + 2 * t;
            const float bx = bias[c], by = bias[c + 1];
            float v0 = acc[i][j][0] + bx, v1 = acc[i][j][1] + by;
            float v2 = acc[i][j][2] + bx, v3 = acc[i][j][3] + by;
            if (ACT == ACT_RELU) {
                v0 = fmaxf(v0, 0.f); v1 = fmaxf(v1, 0.f);
                v2 = fmaxf(v2, 0.f); v3 = fmaxf(v3, 0.f);
            }
            const int r0 = bm + row0 + i * 16 + g;
            if (OUT_HALF) {
                __half2* C = (__half2*)Cout;
                C[((size_t)r0 * N + c) >> 1]       = __floats2half2_rn(v0, v1);
                C[((size_t)(r0 + 8) * N + c) >> 1] = __floats2half2_rn(v2, v3);
            } else {
                float* C = (float*)Cout;
                float2 o0 = {v0, v1}, o1 = {v2, v3};
                *(float2*)&C[(size_t)r0 * N + c]       = o0;
                *(float2*)&C[(size_t)(r0 + 8) * N + c] = o1;
            }
        }
    }
}

// ---------------------------------------------------------------------------
// GRU gate epilogue; writes fp32 h' to output and fp16 copy for head GEMM.
// ---------------------------------------------------------------------------
__device__ __forceinline__ float sigmoidf_(float x) {
    return 1.0f / (1.0f + __expf(-x));
}

__global__ __launch_bounds__(256) void gru_gates_kernel(
    const float* __restrict__ gi, const float* __restrict__ gh,
    const float* __restrict__ h_in, float* __restrict__ h_out,
    __half* __restrict__ h_out_h)
{
    const int idx = blockIdx.x * blockDim.x + threadIdx.x;
    const int row = idx / (H2 / 4);
    const int jc  = (idx % (H2 / 4)) * 4;
    const size_t base = (size_t)row * G3 + jc;

    const float4 ir  = *(const float4*)(gi + base);
    const float4 iz  = *(const float4*)(gi + base + H2);
    const float4 in4 = *(const float4*)(gi + base + 2 * H2);
    const float4 hr  = *(const float4*)(gh + base);
    const float4 hz  = *(const float4*)(gh + base + H2);
    const float4 hn  = *(const float4*)(gh + base + 2 * H2);
    const float4 hv  = *(const float4*)(h_in + (size_t)row * H2 + jc);

    float4 o;
    {
        float r = sigmoidf_(ir.x + hr.x);
        float z = sigmoidf_(iz.x + hz.x);
        float n = tanhf(in4.x + r * hn.x);
        o.x = (1.0f - z) * n + z * hv.x;
    }
    {
        float r = sigmoidf_(ir.y + hr.y);
        float z = sigmoidf_(iz.y + hz.y);
        float n = tanhf(in4.y + r * hn.y);
        o.y = (1.0f - z) * n + z * hv.y;
    }
    {
        float r = sigmoidf_(ir.z + hr.z);
        float z = sigmoidf_(iz.z + hz.z);
        float n = tanhf(in4.z + r * hn.z);
        o.z = (1.0f - z) * n + z * hv.z;
    }
    {
        float r = sigmoidf_(ir.w + hr.w);
        float z = sigmoidf_(iz.w + hz.w);
        float n = tanhf(in4.w + r * hn.w);
        o.w = (1.0f - z) * n + z * hv.w;
    }
    *(float4*)(h_out + (size_t)row * H2 + jc) = o;

    __half2* hh = (__half2*)(h_out_h + (size_t)row * H2 + jc);
    hh[0] = __floats2half2_rn(o.x, o.y);
    hh[1] = __floats2half2_rn(o.z, o.w);
}

// ---------------------------------------------------------------------------
// kernel_launch
// ---------------------------------------------------------------------------
extern "C" void kernel_launch(void* const* d_in, const int* in_sizes, int n_in,
                              void* d_out, int out_size)
{
    const float* inputs = (const float*)d_in[0];
    const float* hidden = (const float*)d_in[1];
    const float* W1     = (const float*)d_in[2];
    const float* b1     = (const float*)d_in[3];
    const float* W_ih   = (const float*)d_in[4];
    const float* W_hh   = (const float*)d_in[5];
    const float* b_ih   = (const float*)d_in[6];
    const float* b_hh   = (const float*)d_in[7];
    const float* W21    = (const float*)d_in[8];
    const float* b21    = (const float*)d_in[9];
    const float* W22    = (const float*)d_in[10];
    const float* b22    = (const float*)d_in[11];

    float* out_q = (float*)d_out;                   // [2B, 32] interleaved
    float* out_h = out_q + (size_t)2 * B_SZ * 32;   // [B, H2]

    __half *inh, *hidh, *xh, *hph, *w1h, *wihh, *whhh, *wcath;
    float *ggi, *ggh, *bcat;
    cudaGetSymbolAddress((void**)&inh,  g_in_h);
    cudaGetSymbolAddress((void**)&hidh, g_hid_h);
    cudaGetSymbolAddress((void**)&xh,   g_x_h);
    cudaGetSymbolAddress((void**)&hph,  g_hp_h);
    cudaGetSymbolAddress((void**)&ggi,  g_gi);
    cudaGetSymbolAddress((void**)&ggh,  g_gh);
    cudaGetSymbolAddress((void**)&w1h,  g_W1h);
    cudaGetSymbolAddress((void**)&wihh, g_Wih_h);
    cudaGetSymbolAddress((void**)&whhh, g_Whh_h);
    cudaGetSymbolAddress((void**)&wcath, g_wcat_h);
    cudaGetSymbolAddress((void**)&bcat, g_bcat);

    // fp32 -> fp16 conversions
    f2h_kernel<<<(B_SZ * IN2 / 4 + 255) / 256, 256>>>(inputs, inh, B_SZ * IN2 / 4);
    f2h_kernel<<<(B_SZ * H2 / 4 + 255) / 256, 256>>>(hidden, hidh, B_SZ * H2 / 4);
    f2h_kernel<<<(H2 * IN2 / 4 + 255) / 256, 256>>>(W1, w1h, H2 * IN2 / 4);
    f2h_kernel<<<(G3 * H2 / 4 + 255) / 256, 256>>>(W_ih, wihh, G3 * H2 / 4);
    f2h_kernel<<<(G3 * H2 / 4 + 255) / 256, 256>>>(W_hh, whhh, G3 * H2 / 4);
    pack_heads_kernel<<<(NQ * H2 + 255) / 256, 256>>>(W21, b21, W22, b22);

    // fc1: x = relu(inputs @ W1^T + b1), fp16 out (pipelined)
    hgemm_kernel<2, 4, ACT_RELU, true, true><<<dim3(H2 / 128, B_SZ / 128), 256>>>(
        inh, w1h, b1, xh, B_SZ, H2, IN2);

    // gi = x @ W_ih^T + b_ih  (fp32 out, pipelined)
    hgemm_kernel<2, 4, ACT_NONE, false, true><<<dim3(G3 / 128, B_SZ / 128), 256>>>(
        xh, wihh, b_ih, ggi, B_SZ, G3, H2);

    // gh = hidden @ W_hh^T + b_hh  (fp32 out, pipelined)
    hgemm_kernel<2, 4, ACT_NONE, false, true><<<dim3(G3 / 128, B_SZ / 128), 256>>>(
        hidh, whhh, b_hh, ggh, B_SZ, G3, H2);

    // gates -> h' (fp32 to output, fp16 copy for heads)
    gru_gates_kernel<<<(B_SZ * H2 / 4) / 256, 256>>>(ggi, ggh, hidden, out_h, hph);

    // q heads: out_q = h' @ Wcat^T + bcat  [B,64] == interleaved q (small, unpipelined)
    hgemm_kernel<4, 2, ACT_NONE, false, false><<<dim3(NQ / 64, B_SZ / 256), 256>>>(
        hph, wcath, bcat, out_q, B_SZ, NQ, H2);
}